// round 16
// baseline (speedup 1.0000x reference)
#include <cuda_runtime.h>
#include <cuda_fp16.h>
#include <cstdint>
#include <math_constants.h>

#define FULLMASK 0xffffffffu

// ---------------- scratch (static device arrays; no cudaMalloc) -------------
static __device__ __half g_xh  [4096u * 4096u];  // x -> half
static __device__ __half g_wcat[6144u * 4096u];  // [wq;wk;wv] rows 0..6143
static __device__ __half g_woh [4096u * 4096u];
static __device__ __half g_q   [4096u * 4096u];  // xq (NOT roped; rope fused in attn)
static __device__ __half g_k   [4096u * 1024u];  // xk (roped in QKV epilogue)
static __device__ __half g_vt  [1024u * 4096u];  // xv TRANSPOSED [hd_global][token]
static __device__ __half g_att [4096u * 4096u];  // attention out

// ---------------- helpers ---------------------------------------------------
__device__ __forceinline__ void mma_f16(float* c, uint32_t a0, uint32_t a1,
                                        uint32_t a2, uint32_t a3,
                                        uint32_t b0, uint32_t b1) {
    asm volatile(
        "mma.sync.aligned.m16n8k16.row.col.f32.f16.f16.f32 "
        "{%0,%1,%2,%3}, {%4,%5,%6,%7}, {%8,%9}, {%0,%1,%2,%3};"
        : "+f"(c[0]), "+f"(c[1]), "+f"(c[2]), "+f"(c[3])
        : "r"(a0), "r"(a1), "r"(a2), "r"(a3), "r"(b0), "r"(b1));
}

__device__ __forceinline__ void cp_async16(void* smem, const void* gmem) {
    uint32_t s = (uint32_t)__cvta_generic_to_shared(smem);
    asm volatile("cp.async.cg.shared.global [%0], [%1], 16;" :: "r"(s), "l"(gmem));
}
__device__ __forceinline__ void cp_commit() {
    asm volatile("cp.async.commit_group;" ::: "memory");
}
template <int N>
__device__ __forceinline__ void cp_wait() {
    asm volatile("cp.async.wait_group %0;" :: "n"(N) : "memory");
}
__device__ __forceinline__ uint32_t h2u(__half2 h) { return *(uint32_t*)&h; }

// ---------------- fused fp32 -> fp16 convert (x, wq|wk|wv -> cat, wo) -------
__global__ void conv_all_kernel(
    __half* xh, const float* x,
    __half* wcat, const float* wq, const float* wk, const float* wv,
    __half* woh, const float* wo)
{
    long long i = (long long)blockIdx.x * blockDim.x + threadIdx.x;
    const float* src; __half* dst; long long off;
    if (i < 1048576)      { src = x;  dst = xh;              off = i; }
    else if (i < 2097152) { src = wq; dst = wcat;            off = i - 1048576; }
    else if (i < 2359296) { src = wk; dst = wcat + 16777216; off = i - 2097152; }
    else if (i < 2621440) { src = wv; dst = wcat + 20971520; off = i - 2359296; }
    else                  { src = wo; dst = woh;             off = i - 2621440; }
    const float4* s4 = (const float4*)src + 4 * off;
    float4 v0 = s4[0], v1 = s4[1], v2 = s4[2], v3 = s4[3];
    uint4 o0, o1;
    o0.x = h2u(__floats2half2_rn(v0.x, v0.y));
    o0.y = h2u(__floats2half2_rn(v0.z, v0.w));
    o0.z = h2u(__floats2half2_rn(v1.x, v1.y));
    o0.w = h2u(__floats2half2_rn(v1.z, v1.w));
    o1.x = h2u(__floats2half2_rn(v2.x, v2.y));
    o1.y = h2u(__floats2half2_rn(v2.z, v2.w));
    o1.z = h2u(__floats2half2_rn(v3.x, v3.y));
    o1.w = h2u(__floats2half2_rn(v3.z, v3.w));
    uint4* d4 = (uint4*)dst + 2 * off;
    d4[0] = o0;
    d4[1] = o1;
}

// ---------------- FP16 GEMM: CTA 128(M) x 64(N), 8 warps of 32x32 ----------
// 5-stage cp.async pipeline. Grid sized for low wave quantization.
// MODE 2: float out row-major. MODE 3: fused-QKV routing by bn; K region
// applies RoPE on fp32 accumulators (single fp16 rounding).
#define GST 12288               // per stage: A 8192 B + B 4096 B
#define NSTG 5
#define GSMEM_BYTES (NSTG * GST)   // 61440

template <int MODE>
__global__ __launch_bounds__(256, 2) void gemm_f16(
    void* Cp, void* Cp2, void* Cp3,
    const __half* __restrict__ A, const __half* __restrict__ B,
    int K, int ldc,
    const float* __restrict__ fc, const float* __restrict__ fs)
{
    extern __shared__ char smem[];
    const int bm = blockIdx.y * 128, bn = blockIdx.x * 64;
    const int tid = threadIdx.x;
    const int warp = tid >> 5, lane = tid & 31;
    const int wm = (warp & 3) << 5;   // 0,32,64,96
    const int wn = (warp >> 2) << 5;  // 0,32
    const int g = lane >> 2, t = lane & 3;

    float acc[2][4][4];
#pragma unroll
    for (int a = 0; a < 2; ++a)
#pragma unroll
        for (int b = 0; b < 4; ++b)
#pragma unroll
            for (int c = 0; c < 4; ++c) acc[a][b][c] = 0.f;

    auto load_stage = [&](int s, int k0) {
        char* SA = smem + s * GST;
        char* SB = SA + 8192;
#pragma unroll
        for (int i = 0; i < 2; ++i) {
            int c = tid + (i << 8);   // 0..511
            int row = c >> 2, sub = c & 3;
            cp_async16(SA + row * 64 + sub * 16, A + (size_t)(bm + row) * K + k0 + sub * 8);
        }
        {
            int row = tid >> 2, sub = tid & 3;   // 64 rows x 4 chunks
            cp_async16(SB + row * 64 + sub * 16, B + (size_t)(bn + row) * K + k0 + sub * 8);
        }
    };

    const int nIter = K >> 5;
    load_stage(0, 0);  cp_commit();
    load_stage(1, 32); cp_commit();
    load_stage(2, 64); cp_commit();
    load_stage(3, 96); cp_commit();

    int cur = 0;
    for (int it = 0; it < nIter; ++it) {
        cp_wait<3>();
        __syncthreads();

        const char* SA = smem + cur * GST;
        const char* SB = SA + 8192;

        uint4 af[2][2];
#pragma unroll
        for (int mt = 0; mt < 2; ++mt) {
            af[mt][0] = *(const uint4*)(SA + (wm + (mt << 4) + g) * 64 + (t << 4));
            af[mt][1] = *(const uint4*)(SA + (wm + (mt << 4) + 8 + g) * 64 + (t << 4));
        }
        uint4 bf[4];
#pragma unroll
        for (int nt = 0; nt < 4; ++nt)
            bf[nt] = *(const uint4*)(SB + (wn + (nt << 3) + g) * 64 + (t << 4));

        {
            int nb = cur - 1; if (nb < 0) nb = NSTG - 1;
            if (it + 4 < nIter) load_stage(nb, (it + 4) << 5);
            cp_commit();
        }

        // 8 independent k0-half MMAs, then 8 k1-half
#pragma unroll
        for (int nt = 0; nt < 4; ++nt) {
            mma_f16(acc[0][nt], af[0][0].x, af[0][1].x, af[0][0].y, af[0][1].y, bf[nt].x, bf[nt].y);
            mma_f16(acc[1][nt], af[1][0].x, af[1][1].x, af[1][0].y, af[1][1].y, bf[nt].x, bf[nt].y);
        }
#pragma unroll
        for (int nt = 0; nt < 4; ++nt) {
            mma_f16(acc[0][nt], af[0][0].z, af[0][1].z, af[0][0].w, af[0][1].w, bf[nt].z, bf[nt].w);
            mma_f16(acc[1][nt], af[1][0].z, af[1][1].z, af[1][0].w, af[1][1].w, bf[nt].z, bf[nt].w);
        }
        if (++cur == NSTG) cur = 0;
    }

    if (MODE == 3) {
        if (bn < 4096) {
            __half* C = (__half*)Cp;   // Q row-major, ldc 4096 (rope applied in attn)
#pragma unroll
            for (int mt = 0; mt < 2; ++mt) {
                int r0 = bm + wm + (mt << 4) + g;
#pragma unroll
                for (int nt = 0; nt < 4; ++nt) {
                    int c0 = bn + wn + (nt << 3) + 2 * t;
                    *(__half2*)&C[(size_t)r0 * 4096 + c0] = __floats2half2_rn(acc[mt][nt][0], acc[mt][nt][1]);
                    *(__half2*)&C[(size_t)(r0 + 8) * 4096 + c0] = __floats2half2_rn(acc[mt][nt][2], acc[mt][nt][3]);
                }
            }
        } else if (bn < 5120) {
            __half* C = (__half*)Cp2;  // K row-major, ldc 1024, FUSED RoPE
#pragma unroll
            for (int mt = 0; mt < 2; ++mt) {
                int r0 = bm + wm + (mt << 4) + g;
                int s0 = r0 & 2047;
#pragma unroll
                for (int nt = 0; nt < 4; ++nt) {
                    int c0 = bn - 4096 + wn + (nt << 3) + 2 * t;
                    int i = (c0 & 127) >> 1;
                    float ca = fc[s0 * 64 + i],       sa = fs[s0 * 64 + i];
                    float cb = fc[(s0 + 8) * 64 + i], sb = fs[(s0 + 8) * 64 + i];
                    float e0 = acc[mt][nt][0] * ca - acc[mt][nt][1] * sa;
                    float o0 = acc[mt][nt][0] * sa + acc[mt][nt][1] * ca;
                    float e1 = acc[mt][nt][2] * cb - acc[mt][nt][3] * sb;
                    float o1 = acc[mt][nt][2] * sb + acc[mt][nt][3] * cb;
                    *(__half2*)&C[(size_t)r0 * 1024 + c0] = __floats2half2_rn(e0, o0);
                    *(__half2*)&C[(size_t)(r0 + 8) * 1024 + c0] = __floats2half2_rn(e1, o1);
                }
            }
        } else {
            __half* C = (__half*)Cp3;  // Vt transposed, ldc 4096 (tokens)
#pragma unroll
            for (int mt = 0; mt < 2; ++mt) {
                int r0 = bm + wm + (mt << 4) + g;
#pragma unroll
                for (int nt = 0; nt < 4; ++nt) {
                    int c0 = bn - 5120 + wn + (nt << 3) + 2 * t;
                    C[(size_t)c0 * 4096 + r0]           = __float2half_rn(acc[mt][nt][0]);
                    C[(size_t)(c0 + 1) * 4096 + r0]     = __float2half_rn(acc[mt][nt][1]);
                    C[(size_t)c0 * 4096 + r0 + 8]       = __float2half_rn(acc[mt][nt][2]);
                    C[(size_t)(c0 + 1) * 4096 + r0 + 8] = __float2half_rn(acc[mt][nt][3]);
                }
            }
        }
    } else {
#pragma unroll
        for (int mt = 0; mt < 2; ++mt) {
            int r0 = bm + wm + (mt << 4) + g;
#pragma unroll
            for (int nt = 0; nt < 4; ++nt) {
                int c0 = bn + wn + (nt << 3) + 2 * t;
                float* C = (float*)Cp;
                *(float2*)&C[(size_t)r0 * ldc + c0] = make_float2(acc[mt][nt][0], acc[mt][nt][1]);
                *(float2*)&C[(size_t)(r0 + 8) * ldc + c0] = make_float2(acc[mt][nt][2], acc[mt][nt][3]);
            }
        }
    }
}

// ---------------- causal GQA flash attention (round-15, passing) ------------
#define QT 64
#define KT 32
#define QSTR 160
#define VSTR 40
#define KBUF 10240
#define ASMEM_BYTES 61440

__global__ __launch_bounds__(128, 3) void attn_kernel(
    __half* __restrict__ O, const __half* __restrict__ Q,
    const __half* __restrict__ Kg, const __half* __restrict__ Vtg,
    const float* __restrict__ fc, const float* __restrict__ fs, float qscale)
{
    extern __shared__ __align__(16) char smem[];

    const int qtile = blockIdx.x;
    const int h = blockIdx.y;
    const int b = blockIdx.z;
    const int kvh = h >> 2;
    const int tid = threadIdx.x;
    const int warp = tid >> 5, lane = tid & 31;
    const int g = lane >> 2, t = lane & 3;
    const int q0 = qtile * QT;

    {
        __half* Qs = (__half*)smem;
#pragma unroll
        for (int j = 0; j < 8; ++j) {
            int c = tid + (j << 7);
            int row = c >> 4, sub = c & 15;
            int s = q0 + row;
            uint4 v = *(const uint4*)&Q[(size_t)(b * 2048 + s) * 4096 + h * 128 + sub * 8];
            float4 c4 = *(const float4*)&fc[(size_t)s * 64 + sub * 4];
            float4 s4 = *(const float4*)&fs[(size_t)s * 64 + sub * 4];
            __half2* hp = (__half2*)&v;
            float2 p0 = __half22float2(hp[0]);
            float2 p1 = __half22float2(hp[1]);
            float2 p2 = __half22float2(hp[2]);
            float2 p3 = __half22float2(hp[3]);
            hp[0] = __floats2half2_rn((p0.x * c4.x - p0.y * s4.x) * qscale,
                                      (p0.x * s4.x + p0.y * c4.x) * qscale);
            hp[1] = __floats2half2_rn((p1.x * c4.y - p1.y * s4.y) * qscale,
                                      (p1.x * s4.y + p1.y * c4.y) * qscale);
            hp[2] = __floats2half2_rn((p2.x * c4.z - p2.y * s4.z) * qscale,
                                      (p2.x * s4.z + p2.y * c4.z) * qscale);
            hp[3] = __floats2half2_rn((p3.x * c4.w - p3.y * s4.w) * qscale,
                                      (p3.x * s4.w + p3.y * c4.w) * qscale);
            *(uint4*)&Qs[row * QSTR + sub * 8] = v;
        }
    }
    __syncthreads();

    uint4 qf[4][2];
    {
        const __half* Qs = (const __half*)smem;
        int r = warp * 16;
#pragma unroll
        for (int c = 0; c < 4; ++c) {
            qf[c][0] = *(const uint4*)&Qs[(r + g) * QSTR + c * 32 + t * 8];
            qf[c][1] = *(const uint4*)&Qs[(r + g + 8) * QSTR + c * 32 + t * 8];
        }
    }
    __syncthreads();

    auto prefetch = [&](int buf, int kv0) {
        char* Kb = smem + buf * KBUF;
        char* Vb = smem + 30720 + buf * KBUF;
#pragma unroll
        for (int j = 0; j < 4; ++j) {
            int c = tid + (j << 7);
            int row = c >> 4, sub = c & 15;
            cp_async16(Kb + row * 320 + sub * 16,
                       &Kg[(size_t)(b * 2048 + kv0 + row) * 1024 + kvh * 128 + sub * 8]);
        }
#pragma unroll
        for (int j = 0; j < 4; ++j) {
            int c = tid + (j << 7);
            int row = c >> 2, sub = c & 3;
            cp_async16(Vb + row * 80 + sub * 16,
                       &Vtg[(size_t)(kvh * 128 + row) * 4096 + b * 2048 + kv0 + sub * 8]);
        }
    };

    const int nTiles = (q0 + QT) / KT;
    prefetch(0, 0);  cp_commit();
    if (nTiles > 1) prefetch(1, KT);
    cp_commit();

    float o[16][4];
#pragma unroll
    for (int i = 0; i < 16; ++i)
#pragma unroll
        for (int j = 0; j < 4; ++j) o[i][j] = 0.f;

    float m0 = -CUDART_INF_F, m1 = -CUDART_INF_F, l0 = 0.f, l1 = 0.f;
    const int rowg0 = q0 + warp * 16 + g;
    const int rowg1 = rowg0 + 8;

    int cur = 0;
    for (int it = 0; it < nTiles; ++it) {
        const int kv0 = it * KT;

        cp_wait<1>();
        __syncthreads();

        const __half* Ks = (const __half*)(smem + cur * KBUF);
        const __half* Vs = (const __half*)(smem + 30720 + cur * KBUF);

        float sv[4][4];
#pragma unroll
        for (int nt = 0; nt < 4; ++nt)
#pragma unroll
            for (int j = 0; j < 4; ++j) sv[nt][j] = 0.f;

#pragma unroll
        for (int c = 0; c < 4; ++c) {
            uint4 kf[4];
#pragma unroll
            for (int nt = 0; nt < 4; ++nt)
                kf[nt] = *(const uint4*)&Ks[(nt * 8 + g) * QSTR + c * 32 + t * 8];
#pragma unroll
            for (int nt = 0; nt < 4; ++nt)
                mma_f16(sv[nt], qf[c][0].x, qf[c][1].x, qf[c][0].y, qf[c][1].y, kf[nt].x, kf[nt].y);
#pragma unroll
            for (int nt = 0; nt < 4; ++nt)
                mma_f16(sv[nt], qf[c][0].z, qf[c][1].z, qf[c][0].w, qf[c][1].w, kf[nt].z, kf[nt].w);
        }

        if (kv0 + KT > q0) {
#pragma unroll
            for (int nt = 0; nt < 4; ++nt) {
                int c0 = kv0 + nt * 8 + 2 * t;
                if (c0 > rowg0) sv[nt][0] = -CUDART_INF_F;
                if (c0 + 1 > rowg0) sv[nt][1] = -CUDART_INF_F;
                if (c0 > rowg1) sv[nt][2] = -CUDART_INF_F;
                if (c0 + 1 > rowg1) sv[nt][3] = -CUDART_INF_F;
            }
        }

        float mx0 = -CUDART_INF_F, mx1 = -CUDART_INF_F;
#pragma unroll
        for (int nt = 0; nt < 4; ++nt) {
            mx0 = fmaxf(mx0, fmaxf(sv[nt][0], sv[nt][1]));
            mx1 = fmaxf(mx1, fmaxf(sv[nt][2], sv[nt][3]));
        }
        mx0 = fmaxf(mx0, __shfl_xor_sync(FULLMASK, mx0, 1));
        mx0 = fmaxf(mx0, __shfl_xor_sync(FULLMASK, mx0, 2));
        mx1 = fmaxf(mx1, __shfl_xor_sync(FULLMASK, mx1, 1));
        mx1 = fmaxf(mx1, __shfl_xor_sync(FULLMASK, mx1, 2));

        float nm0 = fmaxf(m0, mx0), nm1 = fmaxf(m1, mx1);
        float a0 = exp2f(m0 - nm0), a1 = exp2f(m1 - nm1);
        m0 = nm0; m1 = nm1;

        float rs0 = 0.f, rs1 = 0.f;
#pragma unroll
        for (int nt = 0; nt < 4; ++nt) {
            sv[nt][0] = exp2f(sv[nt][0] - m0);
            sv[nt][1] = exp2f(sv[nt][1] - m0);
            sv[nt][2] = exp2f(sv[nt][2] - m1);
            sv[nt][3] = exp2f(sv[nt][3] - m1);
            rs0 += sv[nt][0] + sv[nt][1];
            rs1 += sv[nt][2] + sv[nt][3];
        }
        rs0 += __shfl_xor_sync(FULLMASK, rs0, 1);
        rs0 += __shfl_xor_sync(FULLMASK, rs0, 2);
        rs1 += __shfl_xor_sync(FULLMASK, rs1, 1);
        rs1 += __shfl_xor_sync(FULLMASK, rs1, 2);
        l0 = l0 * a0 + rs0;
        l1 = l1 * a1 + rs1;

        if (!__all_sync(FULLMASK, (a0 == 1.f) && (a1 == 1.f))) {
#pragma unroll
            for (int ht = 0; ht < 16; ++ht) {
                o[ht][0] *= a0; o[ht][1] *= a0;
                o[ht][2] *= a1; o[ht][3] *= a1;
            }
        }

        uint32_t p00 = h2u(__floats2half2_rn(sv[0][0], sv[0][1]));
        uint32_t p01 = h2u(__floats2half2_rn(sv[0][2], sv[0][3]));
        uint32_t p02 = h2u(__floats2half2_rn(sv[1][0], sv[1][1]));
        uint32_t p03 = h2u(__floats2half2_rn(sv[1][2], sv[1][3]));
        uint32_t p10 = h2u(__floats2half2_rn(sv[2][0], sv[2][1]));
        uint32_t p11 = h2u(__floats2half2_rn(sv[2][2], sv[2][3]));
        uint32_t p12 = h2u(__floats2half2_rn(sv[3][0], sv[3][1]));
        uint32_t p13 = h2u(__floats2half2_rn(sv[3][2], sv[3][3]));

#pragma unroll
        for (int ht = 0; ht < 16; ++ht) {
            const __half* vr = &Vs[(8 * ht + g) * VSTR];
            uint32_t b0 = *(const uint32_t*)(vr + 2 * t);
            uint32_t b1 = *(const uint32_t*)(vr + 2 * t + 8);
            mma_f16(o[ht], p00, p01, p02, p03, b0, b1);
        }
#pragma unroll
        for (int ht = 0; ht < 16; ++ht) {
            const __half* vr = &Vs[(8 * ht + g) * VSTR];
            uint32_t b2 = *(const uint32_t*)(vr + 16 + 2 * t);
            uint32_t b3 = *(const uint32_t*)(vr + 16 + 2 * t + 8);
            mma_f16(o[ht], p10, p11, p12, p13, b2, b3);
        }

        {
            int nb = cur + 2; if (nb >= 3) nb -= 3;
            if (it + 2 < nTiles) prefetch(nb, (it + 2) * KT);
            cp_commit();
        }

        if (++cur == 3) cur = 0;
    }

    float i0 = 1.f / l0, i1 = 1.f / l1;
#pragma unroll
    for (int ht = 0; ht < 16; ++ht) {
        size_t base = (size_t)(b * 2048 + rowg0) * 4096 + h * 128 + 8 * ht + 2 * t;
        *(__half2*)&O[base] = __floats2half2_rn(o[ht][0] * i0, o[ht][1] * i0);
        *(__half2*)&O[base + (size_t)8 * 4096] = __floats2half2_rn(o[ht][2] * i1, o[ht][3] * i1);
    }
}

// ---------------- entry -----------------------------------------------------
extern "C" void kernel_launch(void* const* d_in, const int* in_sizes, int n_in,
                              void* d_out, int out_size)
{
    const float* x  = (const float*)d_in[0];
    const float* wq = (const float*)d_in[1];
    const float* wk = (const float*)d_in[2];
    const float* wv = (const float*)d_in[3];
    const float* wo = (const float*)d_in[4];
    const float* fc = (const float*)d_in[5];
    const float* fs = (const float*)d_in[6];
    float* out = (float*)d_out;

    __half *xh, *wcat, *woh, *q, *k, *vt, *att;
    cudaGetSymbolAddress((void**)&xh,   g_xh);
    cudaGetSymbolAddress((void**)&wcat, g_wcat);
    cudaGetSymbolAddress((void**)&woh,  g_woh);
    cudaGetSymbolAddress((void**)&q,    g_q);
    cudaGetSymbolAddress((void**)&k,    g_k);
    cudaGetSymbolAddress((void**)&vt,   g_vt);
    cudaGetSymbolAddress((void**)&att,  g_att);

    cudaFuncSetAttribute(gemm_f16<2>, cudaFuncAttributeMaxDynamicSharedMemorySize, GSMEM_BYTES);
    cudaFuncSetAttribute(gemm_f16<3>, cudaFuncAttributeMaxDynamicSharedMemorySize, GSMEM_BYTES);
    cudaFuncSetAttribute(attn_kernel, cudaFuncAttributeMaxDynamicSharedMemorySize, ASMEM_BYTES);

    const float qscale = 0.08838834764831845f * 1.4426950408889634f;

    // 1: fused convert (x, wq|wk|wv -> wcat, wo)
    conv_all_kernel<<<14336, 256>>>(xh, x, wcat, wq, wk, wv, woh, wo);

    // 2: fused QKV projection (128x64 tiles; Q plain, K + RoPE, V transpose)
    gemm_f16<3><<<dim3(96, 32), 256, GSMEM_BYTES>>>(q, k, vt, xh, wcat, 4096, 0, fc, fs);

    // 3: attention (fused Q rope + scale, 1-barrier ring) -> g_att (half)
    attn_kernel<<<dim3(32, 32, 2), 128, ASMEM_BYTES>>>(att, q, k, vt, fc, fs, qscale);

    // 4 (profiled slot): output projection (128x64 tiles) -> d_out (fp32)
    gemm_f16<2><<<dim3(64, 32), 256, GSMEM_BYTES>>>(out, nullptr, nullptr, att, woh, 4096, 4096, nullptr, nullptr);
}

// round 17
// speedup vs baseline: 1.0236x; 1.0236x over previous
#include <cuda_runtime.h>
#include <cuda_fp16.h>
#include <cstdint>
#include <math_constants.h>

#define FULLMASK 0xffffffffu

// ---------------- scratch (static device arrays; no cudaMalloc) -------------
static __device__ __half g_xh  [4096u * 4096u];  // x -> half
static __device__ __half g_wcat[6144u * 4096u];  // [wq;wk;wv] rows 0..6143
static __device__ __half g_woh [4096u * 4096u];
static __device__ __half g_q   [4096u * 4096u];  // xq (NOT roped; rope fused in attn)
static __device__ __half g_k   [4096u * 1024u];  // xk (roped in QKV epilogue)
static __device__ __half g_vt  [1024u * 4096u];  // xv TRANSPOSED [hd_global][token]
static __device__ __half g_att [4096u * 4096u];  // attention out

// ---------------- helpers ---------------------------------------------------
__device__ __forceinline__ void mma_f16(float* c, uint32_t a0, uint32_t a1,
                                        uint32_t a2, uint32_t a3,
                                        uint32_t b0, uint32_t b1) {
    asm volatile(
        "mma.sync.aligned.m16n8k16.row.col.f32.f16.f16.f32 "
        "{%0,%1,%2,%3}, {%4,%5,%6,%7}, {%8,%9}, {%0,%1,%2,%3};"
        : "+f"(c[0]), "+f"(c[1]), "+f"(c[2]), "+f"(c[3])
        : "r"(a0), "r"(a1), "r"(a2), "r"(a3), "r"(b0), "r"(b1));
}

__device__ __forceinline__ void cp_async16(void* smem, const void* gmem) {
    uint32_t s = (uint32_t)__cvta_generic_to_shared(smem);
    asm volatile("cp.async.cg.shared.global [%0], [%1], 16;" :: "r"(s), "l"(gmem));
}
__device__ __forceinline__ void cp_commit() {
    asm volatile("cp.async.commit_group;" ::: "memory");
}
template <int N>
__device__ __forceinline__ void cp_wait() {
    asm volatile("cp.async.wait_group %0;" :: "n"(N) : "memory");
}
__device__ __forceinline__ uint32_t h2u(__half2 h) { return *(uint32_t*)&h; }

// ---------------- fused fp32 -> fp16 convert (x, wq|wk|wv -> cat, wo) -------
__global__ void conv_all_kernel(
    __half* xh, const float* x,
    __half* wcat, const float* wq, const float* wk, const float* wv,
    __half* woh, const float* wo)
{
    long long i = (long long)blockIdx.x * blockDim.x + threadIdx.x;
    const float* src; __half* dst; long long off;
    if (i < 1048576)      { src = x;  dst = xh;              off = i; }
    else if (i < 2097152) { src = wq; dst = wcat;            off = i - 1048576; }
    else if (i < 2359296) { src = wk; dst = wcat + 16777216; off = i - 2097152; }
    else if (i < 2621440) { src = wv; dst = wcat + 20971520; off = i - 2359296; }
    else                  { src = wo; dst = woh;             off = i - 2621440; }
    const float4* s4 = (const float4*)src + 4 * off;
    float4 v0 = s4[0], v1 = s4[1], v2 = s4[2], v3 = s4[3];
    uint4 o0, o1;
    o0.x = h2u(__floats2half2_rn(v0.x, v0.y));
    o0.y = h2u(__floats2half2_rn(v0.z, v0.w));
    o0.z = h2u(__floats2half2_rn(v1.x, v1.y));
    o0.w = h2u(__floats2half2_rn(v1.z, v1.w));
    o1.x = h2u(__floats2half2_rn(v2.x, v2.y));
    o1.y = h2u(__floats2half2_rn(v2.z, v2.w));
    o1.z = h2u(__floats2half2_rn(v3.x, v3.y));
    o1.w = h2u(__floats2half2_rn(v3.z, v3.w));
    uint4* d4 = (uint4*)dst + 2 * off;
    d4[0] = o0;
    d4[1] = o1;
}

// ---------------- FP16 GEMM: CTA 128x128, 8 warps of 32x64 (round-15) -------
// MODE 2: float out row-major. MODE 3: fused-QKV routing by bn; K region
// applies RoPE on fp32 accumulators (single fp16 rounding).
#define GST 16384
#define NSTG 5
#define GSMEM_BYTES (NSTG * GST)   // 81920

template <int MODE>
__global__ __launch_bounds__(256, 2) void gemm_f16(
    void* Cp, void* Cp2, void* Cp3,
    const __half* __restrict__ A, const __half* __restrict__ B,
    int K, int ldc,
    const float* __restrict__ fc, const float* __restrict__ fs)
{
    extern __shared__ char smem[];
    const int bm = blockIdx.y * 128, bn = blockIdx.x * 128;
    const int tid = threadIdx.x;
    const int warp = tid >> 5, lane = tid & 31;
    const int wm = (warp & 3) << 5;
    const int wn = (warp >> 2) << 6;
    const int g = lane >> 2, t = lane & 3;

    float acc[2][8][4];
#pragma unroll
    for (int a = 0; a < 2; ++a)
#pragma unroll
        for (int b = 0; b < 8; ++b)
#pragma unroll
            for (int c = 0; c < 4; ++c) acc[a][b][c] = 0.f;

    auto load_stage = [&](int s, int k0) {
        char* SA = smem + s * GST;
        char* SB = SA + 8192;
#pragma unroll
        for (int i = 0; i < 2; ++i) {
            int c = tid + (i << 8);
            int row = c >> 2, sub = c & 3;
            cp_async16(SA + row * 64 + sub * 16, A + (size_t)(bm + row) * K + k0 + sub * 8);
        }
#pragma unroll
        for (int i = 0; i < 2; ++i) {
            int c = tid + (i << 8);
            int row = c >> 2, sub = c & 3;
            cp_async16(SB + row * 64 + sub * 16, B + (size_t)(bn + row) * K + k0 + sub * 8);
        }
    };

    const int nIter = K >> 5;
    load_stage(0, 0);  cp_commit();
    load_stage(1, 32); cp_commit();
    load_stage(2, 64); cp_commit();
    load_stage(3, 96); cp_commit();

    int cur = 0;
    for (int it = 0; it < nIter; ++it) {
        cp_wait<3>();
        __syncthreads();

        const char* SA = smem + cur * GST;
        const char* SB = SA + 8192;

        uint4 af[2][2];
#pragma unroll
        for (int mt = 0; mt < 2; ++mt) {
            af[mt][0] = *(const uint4*)(SA + (wm + (mt << 4) + g) * 64 + (t << 4));
            af[mt][1] = *(const uint4*)(SA + (wm + (mt << 4) + 8 + g) * 64 + (t << 4));
        }

        {
            int nb = cur - 1; if (nb < 0) nb = NSTG - 1;
            if (it + 4 < nIter) load_stage(nb, (it + 4) << 5);
            cp_commit();
        }

#pragma unroll
        for (int hgrp = 0; hgrp < 2; ++hgrp) {
            uint4 bf[4];
#pragma unroll
            for (int j = 0; j < 4; ++j)
                bf[j] = *(const uint4*)(SB + (wn + ((hgrp * 4 + j) << 3) + g) * 64 + (t << 4));
#pragma unroll
            for (int j = 0; j < 4; ++j) {
                int nt = hgrp * 4 + j;
                mma_f16(acc[0][nt], af[0][0].x, af[0][1].x, af[0][0].y, af[0][1].y, bf[j].x, bf[j].y);
                mma_f16(acc[1][nt], af[1][0].x, af[1][1].x, af[1][0].y, af[1][1].y, bf[j].x, bf[j].y);
            }
#pragma unroll
            for (int j = 0; j < 4; ++j) {
                int nt = hgrp * 4 + j;
                mma_f16(acc[0][nt], af[0][0].z, af[0][1].z, af[0][0].w, af[0][1].w, bf[j].z, bf[j].w);
                mma_f16(acc[1][nt], af[1][0].z, af[1][1].z, af[1][0].w, af[1][1].w, bf[j].z, bf[j].w);
            }
        }
        if (++cur == NSTG) cur = 0;
    }

    if (MODE == 3) {
        if (bn < 4096) {
            __half* C = (__half*)Cp;   // Q row-major, ldc 4096 (rope applied in attn)
#pragma unroll
            for (int mt = 0; mt < 2; ++mt) {
                int r0 = bm + wm + (mt << 4) + g;
#pragma unroll
                for (int nt = 0; nt < 8; ++nt) {
                    int c0 = bn + wn + (nt << 3) + 2 * t;
                    *(__half2*)&C[(size_t)r0 * 4096 + c0] = __floats2half2_rn(acc[mt][nt][0], acc[mt][nt][1]);
                    *(__half2*)&C[(size_t)(r0 + 8) * 4096 + c0] = __floats2half2_rn(acc[mt][nt][2], acc[mt][nt][3]);
                }
            }
        } else if (bn < 5120) {
            __half* C = (__half*)Cp2;  // K row-major, ldc 1024, FUSED RoPE
#pragma unroll
            for (int mt = 0; mt < 2; ++mt) {
                int r0 = bm + wm + (mt << 4) + g;
                int s0 = r0 & 2047;
#pragma unroll
                for (int nt = 0; nt < 8; ++nt) {
                    int c0 = bn - 4096 + wn + (nt << 3) + 2 * t;
                    int i = (c0 & 127) >> 1;
                    float ca = fc[s0 * 64 + i],       sa = fs[s0 * 64 + i];
                    float cb = fc[(s0 + 8) * 64 + i], sb = fs[(s0 + 8) * 64 + i];
                    float e0 = acc[mt][nt][0] * ca - acc[mt][nt][1] * sa;
                    float o0 = acc[mt][nt][0] * sa + acc[mt][nt][1] * ca;
                    float e1 = acc[mt][nt][2] * cb - acc[mt][nt][3] * sb;
                    float o1 = acc[mt][nt][2] * sb + acc[mt][nt][3] * cb;
                    *(__half2*)&C[(size_t)r0 * 1024 + c0] = __floats2half2_rn(e0, o0);
                    *(__half2*)&C[(size_t)(r0 + 8) * 1024 + c0] = __floats2half2_rn(e1, o1);
                }
            }
        } else {
            __half* C = (__half*)Cp3;  // Vt transposed, ldc 4096 (tokens)
#pragma unroll
            for (int mt = 0; mt < 2; ++mt) {
                int r0 = bm + wm + (mt << 4) + g;
#pragma unroll
                for (int nt = 0; nt < 8; ++nt) {
                    int c0 = bn - 5120 + wn + (nt << 3) + 2 * t;
                    C[(size_t)c0 * 4096 + r0]           = __float2half_rn(acc[mt][nt][0]);
                    C[(size_t)(c0 + 1) * 4096 + r0]     = __float2half_rn(acc[mt][nt][1]);
                    C[(size_t)c0 * 4096 + r0 + 8]       = __float2half_rn(acc[mt][nt][2]);
                    C[(size_t)(c0 + 1) * 4096 + r0 + 8] = __float2half_rn(acc[mt][nt][3]);
                }
            }
        }
    } else {
#pragma unroll
        for (int mt = 0; mt < 2; ++mt) {
            int r0 = bm + wm + (mt << 4) + g;
#pragma unroll
            for (int nt = 0; nt < 8; ++nt) {
                int c0 = bn + wn + (nt << 3) + 2 * t;
                float* C = (float*)Cp;
                *(float2*)&C[(size_t)r0 * ldc + c0] = make_float2(acc[mt][nt][0], acc[mt][nt][1]);
                *(float2*)&C[(size_t)(r0 + 8) * ldc + c0] = make_float2(acc[mt][nt][2], acc[mt][nt][3]);
            }
        }
    }
}

// ---------------- causal GQA flash attention (round-15 + heavy-first) -------
#define QT 64
#define KT 32
#define QSTR 160
#define VSTR 40
#define KBUF 10240
#define ASMEM_BYTES 61440

__global__ __launch_bounds__(128, 3) void attn_kernel(
    __half* __restrict__ O, const __half* __restrict__ Q,
    const __half* __restrict__ Kg, const __half* __restrict__ Vtg,
    const float* __restrict__ fc, const float* __restrict__ fs, float qscale)
{
    extern __shared__ __align__(16) char smem[];

    const int qtile = (int)gridDim.x - 1 - (int)blockIdx.x;  // heavy first (LPT)
    const int h = blockIdx.y;
    const int b = blockIdx.z;
    const int kvh = h >> 2;
    const int tid = threadIdx.x;
    const int warp = tid >> 5, lane = tid & 31;
    const int g = lane >> 2, t = lane & 3;
    const int q0 = qtile * QT;

    {
        __half* Qs = (__half*)smem;
#pragma unroll
        for (int j = 0; j < 8; ++j) {
            int c = tid + (j << 7);
            int row = c >> 4, sub = c & 15;
            int s = q0 + row;
            uint4 v = *(const uint4*)&Q[(size_t)(b * 2048 + s) * 4096 + h * 128 + sub * 8];
            float4 c4 = *(const float4*)&fc[(size_t)s * 64 + sub * 4];
            float4 s4 = *(const float4*)&fs[(size_t)s * 64 + sub * 4];
            __half2* hp = (__half2*)&v;
            float2 p0 = __half22float2(hp[0]);
            float2 p1 = __half22float2(hp[1]);
            float2 p2 = __half22float2(hp[2]);
            float2 p3 = __half22float2(hp[3]);
            hp[0] = __floats2half2_rn((p0.x * c4.x - p0.y * s4.x) * qscale,
                                      (p0.x * s4.x + p0.y * c4.x) * qscale);
            hp[1] = __floats2half2_rn((p1.x * c4.y - p1.y * s4.y) * qscale,
                                      (p1.x * s4.y + p1.y * c4.y) * qscale);
            hp[2] = __floats2half2_rn((p2.x * c4.z - p2.y * s4.z) * qscale,
                                      (p2.x * s4.z + p2.y * c4.z) * qscale);
            hp[3] = __floats2half2_rn((p3.x * c4.w - p3.y * s4.w) * qscale,
                                      (p3.x * s4.w + p3.y * c4.w) * qscale);
            *(uint4*)&Qs[row * QSTR + sub * 8] = v;
        }
    }
    __syncthreads();

    uint4 qf[4][2];
    {
        const __half* Qs = (const __half*)smem;
        int r = warp * 16;
#pragma unroll
        for (int c = 0; c < 4; ++c) {
            qf[c][0] = *(const uint4*)&Qs[(r + g) * QSTR + c * 32 + t * 8];
            qf[c][1] = *(const uint4*)&Qs[(r + g + 8) * QSTR + c * 32 + t * 8];
        }
    }
    __syncthreads();

    auto prefetch = [&](int buf, int kv0) {
        char* Kb = smem + buf * KBUF;
        char* Vb = smem + 30720 + buf * KBUF;
#pragma unroll
        for (int j = 0; j < 4; ++j) {
            int c = tid + (j << 7);
            int row = c >> 4, sub = c & 15;
            cp_async16(Kb + row * 320 + sub * 16,
                       &Kg[(size_t)(b * 2048 + kv0 + row) * 1024 + kvh * 128 + sub * 8]);
        }
#pragma unroll
        for (int j = 0; j < 4; ++j) {
            int c = tid + (j << 7);
            int row = c >> 2, sub = c & 3;
            cp_async16(Vb + row * 80 + sub * 16,
                       &Vtg[(size_t)(kvh * 128 + row) * 4096 + b * 2048 + kv0 + sub * 8]);
        }
    };

    const int nTiles = (q0 + QT) / KT;
    prefetch(0, 0);  cp_commit();
    if (nTiles > 1) prefetch(1, KT);
    cp_commit();

    float o[16][4];
#pragma unroll
    for (int i = 0; i < 16; ++i)
#pragma unroll
        for (int j = 0; j < 4; ++j) o[i][j] = 0.f;

    float m0 = -CUDART_INF_F, m1 = -CUDART_INF_F, l0 = 0.f, l1 = 0.f;
    const int rowg0 = q0 + warp * 16 + g;
    const int rowg1 = rowg0 + 8;

    int cur = 0;
    for (int it = 0; it < nTiles; ++it) {
        const int kv0 = it * KT;

        cp_wait<1>();
        __syncthreads();

        const __half* Ks = (const __half*)(smem + cur * KBUF);
        const __half* Vs = (const __half*)(smem + 30720 + cur * KBUF);

        float sv[4][4];
#pragma unroll
        for (int nt = 0; nt < 4; ++nt)
#pragma unroll
            for (int j = 0; j < 4; ++j) sv[nt][j] = 0.f;

#pragma unroll
        for (int c = 0; c < 4; ++c) {
            uint4 kf[4];
#pragma unroll
            for (int nt = 0; nt < 4; ++nt)
                kf[nt] = *(const uint4*)&Ks[(nt * 8 + g) * QSTR + c * 32 + t * 8];
#pragma unroll
            for (int nt = 0; nt < 4; ++nt)
                mma_f16(sv[nt], qf[c][0].x, qf[c][1].x, qf[c][0].y, qf[c][1].y, kf[nt].x, kf[nt].y);
#pragma unroll
            for (int nt = 0; nt < 4; ++nt)
                mma_f16(sv[nt], qf[c][0].z, qf[c][1].z, qf[c][0].w, qf[c][1].w, kf[nt].z, kf[nt].w);
        }

        if (kv0 + KT > q0) {
#pragma unroll
            for (int nt = 0; nt < 4; ++nt) {
                int c0 = kv0 + nt * 8 + 2 * t;
                if (c0 > rowg0) sv[nt][0] = -CUDART_INF_F;
                if (c0 + 1 > rowg0) sv[nt][1] = -CUDART_INF_F;
                if (c0 > rowg1) sv[nt][2] = -CUDART_INF_F;
                if (c0 + 1 > rowg1) sv[nt][3] = -CUDART_INF_F;
            }
        }

        float mx0 = -CUDART_INF_F, mx1 = -CUDART_INF_F;
#pragma unroll
        for (int nt = 0; nt < 4; ++nt) {
            mx0 = fmaxf(mx0, fmaxf(sv[nt][0], sv[nt][1]));
            mx1 = fmaxf(mx1, fmaxf(sv[nt][2], sv[nt][3]));
        }
        mx0 = fmaxf(mx0, __shfl_xor_sync(FULLMASK, mx0, 1));
        mx0 = fmaxf(mx0, __shfl_xor_sync(FULLMASK, mx0, 2));
        mx1 = fmaxf(mx1, __shfl_xor_sync(FULLMASK, mx1, 1));
        mx1 = fmaxf(mx1, __shfl_xor_sync(FULLMASK, mx1, 2));

        float nm0 = fmaxf(m0, mx0), nm1 = fmaxf(m1, mx1);
        float a0 = exp2f(m0 - nm0), a1 = exp2f(m1 - nm1);
        m0 = nm0; m1 = nm1;

        float rs0 = 0.f, rs1 = 0.f;
#pragma unroll
        for (int nt = 0; nt < 4; ++nt) {
            sv[nt][0] = exp2f(sv[nt][0] - m0);
            sv[nt][1] = exp2f(sv[nt][1] - m0);
            sv[nt][2] = exp2f(sv[nt][2] - m1);
            sv[nt][3] = exp2f(sv[nt][3] - m1);
            rs0 += sv[nt][0] + sv[nt][1];
            rs1 += sv[nt][2] + sv[nt][3];
        }
        rs0 += __shfl_xor_sync(FULLMASK, rs0, 1);
        rs0 += __shfl_xor_sync(FULLMASK, rs0, 2);
        rs1 += __shfl_xor_sync(FULLMASK, rs1, 1);
        rs1 += __shfl_xor_sync(FULLMASK, rs1, 2);
        l0 = l0 * a0 + rs0;
        l1 = l1 * a1 + rs1;

        if (!__all_sync(FULLMASK, (a0 == 1.f) && (a1 == 1.f))) {
#pragma unroll
            for (int ht = 0; ht < 16; ++ht) {
                o[ht][0] *= a0; o[ht][1] *= a0;
                o[ht][2] *= a1; o[ht][3] *= a1;
            }
        }

        uint32_t p00 = h2u(__floats2half2_rn(sv[0][0], sv[0][1]));
        uint32_t p01 = h2u(__floats2half2_rn(sv[0][2], sv[0][3]));
        uint32_t p02 = h2u(__floats2half2_rn(sv[1][0], sv[1][1]));
        uint32_t p03 = h2u(__floats2half2_rn(sv[1][2], sv[1][3]));
        uint32_t p10 = h2u(__floats2half2_rn(sv[2][0], sv[2][1]));
        uint32_t p11 = h2u(__floats2half2_rn(sv[2][2], sv[2][3]));
        uint32_t p12 = h2u(__floats2half2_rn(sv[3][0], sv[3][1]));
        uint32_t p13 = h2u(__floats2half2_rn(sv[3][2], sv[3][3]));

#pragma unroll
        for (int ht = 0; ht < 16; ++ht) {
            const __half* vr = &Vs[(8 * ht + g) * VSTR];
            uint32_t b0 = *(const uint32_t*)(vr + 2 * t);
            uint32_t b1 = *(const uint32_t*)(vr + 2 * t + 8);
            mma_f16(o[ht], p00, p01, p02, p03, b0, b1);
        }
#pragma unroll
        for (int ht = 0; ht < 16; ++ht) {
            const __half* vr = &Vs[(8 * ht + g) * VSTR];
            uint32_t b2 = *(const uint32_t*)(vr + 16 + 2 * t);
            uint32_t b3 = *(const uint32_t*)(vr + 16 + 2 * t + 8);
            mma_f16(o[ht], p10, p11, p12, p13, b2, b3);
        }

        {
            int nb = cur + 2; if (nb >= 3) nb -= 3;
            if (it + 2 < nTiles) prefetch(nb, (it + 2) * KT);
            cp_commit();
        }

        if (++cur == 3) cur = 0;
    }

    float i0 = 1.f / l0, i1 = 1.f / l1;
#pragma unroll
    for (int ht = 0; ht < 16; ++ht) {
        size_t base = (size_t)(b * 2048 + rowg0) * 4096 + h * 128 + 8 * ht + 2 * t;
        *(__half2*)&O[base] = __floats2half2_rn(o[ht][0] * i0, o[ht][1] * i0);
        *(__half2*)&O[base + (size_t)8 * 4096] = __floats2half2_rn(o[ht][2] * i1, o[ht][3] * i1);
    }
}

// ---------------- entry -----------------------------------------------------
extern "C" void kernel_launch(void* const* d_in, const int* in_sizes, int n_in,
                              void* d_out, int out_size)
{
    const float* x  = (const float*)d_in[0];
    const float* wq = (const float*)d_in[1];
    const float* wk = (const float*)d_in[2];
    const float* wv = (const float*)d_in[3];
    const float* wo = (const float*)d_in[4];
    const float* fc = (const float*)d_in[5];
    const float* fs = (const float*)d_in[6];
    float* out = (float*)d_out;

    __half *xh, *wcat, *woh, *q, *k, *vt, *att;
    cudaGetSymbolAddress((void**)&xh,   g_xh);
    cudaGetSymbolAddress((void**)&wcat, g_wcat);
    cudaGetSymbolAddress((void**)&woh,  g_woh);
    cudaGetSymbolAddress((void**)&q,    g_q);
    cudaGetSymbolAddress((void**)&k,    g_k);
    cudaGetSymbolAddress((void**)&vt,   g_vt);
    cudaGetSymbolAddress((void**)&att,  g_att);

    cudaFuncSetAttribute(gemm_f16<2>, cudaFuncAttributeMaxDynamicSharedMemorySize, GSMEM_BYTES);
    cudaFuncSetAttribute(gemm_f16<3>, cudaFuncAttributeMaxDynamicSharedMemorySize, GSMEM_BYTES);
    cudaFuncSetAttribute(attn_kernel, cudaFuncAttributeMaxDynamicSharedMemorySize, ASMEM_BYTES);

    const float qscale = 0.08838834764831845f * 1.4426950408889634f;

    // 1: fused convert (x, wq|wk|wv -> wcat, wo)
    conv_all_kernel<<<14336, 256>>>(xh, x, wcat, wq, wk, wv, woh, wo);

    // 2: fused QKV projection (128x128 tiles; Q plain, K + RoPE, V transpose)
    gemm_f16<3><<<dim3(48, 32), 256, GSMEM_BYTES>>>(q, k, vt, xh, wcat, 4096, 0, fc, fs);

    // 3: attention (fused Q rope + scale, heavy-first) -> g_att (half)
    attn_kernel<<<dim3(32, 32, 2), 128, ASMEM_BYTES>>>(att, q, k, vt, fc, fs, qscale);

    // 4 (profiled slot): output projection -> d_out (fp32)
    gemm_f16<2><<<dim3(32, 32), 256, GSMEM_BYTES>>>(out, nullptr, nullptr, att, woh, 4096, 4096, nullptr, nullptr);
}